// round 12
// baseline (speedup 1.0000x reference)
#include <cuda_runtime.h>
#include <cuda_fp16.h>
#include <cstdint>

#define Bc 2048
#define Tc 256
#define Ic 64
#define Hc 128
#define Gc 512
#define Mc (Bc * Tc)

// ---------------------------------------------------------------------------
// Scratch (device globals; no allocation allowed)
// ---------------------------------------------------------------------------
__device__ __half g_seq0[(size_t)Mc * Hc];       // layer0 hidden [B][T][H]
__device__ __half g_seq1[(size_t)Mc * Hc];       // layer1 hidden [B][T][H]
__device__ float  g_ctx[(size_t)Bc * Hc];        // attention context [B][128]
__device__ uint2  g_wf0[4 * 4 * 16 * 32];        // w_ih0 frag-ordered (K=64)
__device__ uint2  g_wf1[8 * 4 * 16 * 32];        // w_ih1 frag-ordered (K=128)
__device__ uint2  g_wfa[8 * 16 * 32];            // aw1 frag-ordered (128x128)

// ---------------------------------------------------------------------------
// PTX helpers
// ---------------------------------------------------------------------------
__device__ __forceinline__ uint32_t su32(const void* p) {
    return (uint32_t)__cvta_generic_to_shared(p);
}
__device__ __forceinline__ void ldsm4(uint32_t a, uint32_t& r0, uint32_t& r1,
                                      uint32_t& r2, uint32_t& r3) {
    asm volatile("ldmatrix.sync.aligned.m8n8.x4.shared.b16 {%0,%1,%2,%3},[%4];"
                 : "=r"(r0), "=r"(r1), "=r"(r2), "=r"(r3) : "r"(a));
}
__device__ __forceinline__ void mma16816(float* d, const uint32_t* a, const uint32_t* b) {
    asm volatile(
        "mma.sync.aligned.m16n8k16.row.col.f32.f16.f16.f32 "
        "{%0,%1,%2,%3},{%4,%5,%6,%7},{%8,%9},{%0,%1,%2,%3};"
        : "+f"(d[0]), "+f"(d[1]), "+f"(d[2]), "+f"(d[3])
        : "r"(a[0]), "r"(a[1]), "r"(a[2]), "r"(a[3]), "r"(b[0]), "r"(b[1]));
}
__device__ __forceinline__ float tanh_f(float x) {
    float y; asm("tanh.approx.f32 %0,%1;" : "=f"(y) : "f"(x)); return y;
}
__device__ __forceinline__ float sig_f(float x) {
    return fmaf(tanh_f(0.5f * x), 0.5f, 0.5f);
}
__device__ __forceinline__ void cpa16(uint32_t d, const void* s) {
    asm volatile("cp.async.cg.shared.global [%0],[%1],16;" :: "r"(d), "l"(s));
}
// load float2 from smem, pack to half2 (register-side fp32->fp16 convert)
__device__ __forceinline__ uint32_t f2h2(const float* p) {
    float2 v = *(const float2*)p;
    __half2 h = __floats2half2_rn(v.x, v.y);
    return *(uint32_t*)&h;
}

// ---------------------------------------------------------------------------
// Fragment-order weight prep:  W[512][K] fp32 -> [kt][g][warp][lane]{2xu32}
// ---------------------------------------------------------------------------
template <int KT>
__global__ __launch_bounds__(256)
void fragprep(const float* __restrict__ W, uint2* __restrict__ out)
{
    int idx = blockIdx.x * 256 + threadIdx.x;
    if (idx >= KT * 4 * 16 * 32) return;
    int lane = idx & 31;
    int rest = idx >> 5;
    int w  = rest & 15; rest >>= 4;
    int g  = rest & 3;
    int kt = rest >> 2;
    int n  = 128 * g + 8 * w + (lane >> 2);
    int k0 = kt * 16 + 2 * (lane & 3);
    const float* row = W + (size_t)n * (KT * 16);
    __half2 v0 = __floats2half2_rn(row[k0],     row[k0 + 1]);
    __half2 v1 = __floats2half2_rn(row[k0 + 8], row[k0 + 9]);
    out[idx] = make_uint2(*(uint32_t*)&v0, *(uint32_t*)&v1);
}

// aw1 [128][128] fp32 -> B-frags [kt(8)][ntile(16)][lane(32)]{2xu32}
__global__ __launch_bounds__(256)
void fragprep_a(const float* __restrict__ W, uint2* __restrict__ out)
{
    int idx = blockIdx.x * 256 + threadIdx.x;   // 4096 total
    int lane = idx & 31;
    int rest = idx >> 5;
    int nt = rest & 15;
    int kt = rest >> 4;
    int n  = nt * 8 + (lane >> 2);
    int k0 = kt * 16 + 2 * (lane & 3);
    const float* row = W + (size_t)n * 128;
    __half2 v0 = __floats2half2_rn(row[k0],     row[k0 + 1]);
    __half2 v1 = __floats2half2_rn(row[k0 + 8], row[k0 + 9]);
    out[idx] = make_uint2(*(uint32_t*)&v0, *(uint32_t*)&v1);
}

// ---------------------------------------------------------------------------
// Fused LSTM layer. AF32=true: input is raw fp32 (layer 0); x is staged fp32
// in smem and A-fragments are packed to fp16 in registers (no ldmatrix, no
// fp16 staging, no extra barrier). AF32=false: fp16 input (layer 1), R11 path.
// ---------------------------------------------------------------------------
template <int KT_IH, bool AF32>   // <4,true> layer0 ; <8,false> layer1
__global__ __launch_bounds__(512, 1)
void lstm_fused(const void* __restrict__ inraw,    // [B][T][K] fp32 or fp16
                const uint2* __restrict__ wfrag,   // [KT_IH][4][16][32]
                const float* __restrict__ w_hh,    // [512][128]
                const float* __restrict__ b_ih,
                const float* __restrict__ b_hh,
                __half* __restrict__ seqout)       // [B][T][128]
{
    constexpr int K   = KT_IH * 16;
    constexpr int KP  = K + 8;            // fp16 staging pitch (halves)
    constexpr int CH  = K / 8;            // fp16 16B chunks per row
    constexpr int KP32 = K + 8;           // fp32 staging pitch (floats), K=64 -> 72
    constexpr int CH32 = K / 4;           // fp32 16B chunks per row (16 for K=64)
    constexpr int WF  = KT_IH * 4 * 16 * 32;

    extern __shared__ char smr[];
    uint2*  wf_sm = (uint2*)smr;                        // [WF]
    __half* h_sm  = (__half*)(wf_sm + WF);              // [2][16][136]
    // staging after h_sm:
    __half* sbuf   = h_sm + 2 * 16 * 136;               // fp16 path: [2][2][16][KP]
    float*  xs32   = (float*)(h_sm + 2 * 16 * 136);     // fp32 path: [2][2][16][KP32]
    float*  bias   = AF32
        ? (float*)(xs32 + 2 * 2 * 16 * KP32)
        : (float*)(sbuf + 2 * 2 * 16 * KP);             // [512]

    const float* in32 = (const float*)inraw;
    const __half* in16 = (const __half*)inraw;

    const int tid = threadIdx.x, wid = tid >> 5, lane = tid & 31;
    const int b0 = blockIdx.x * 16;
    const int mat = lane >> 3, lr = lane & 7;
    const int r_lo = lane >> 2, c_loc = 2 * (lane & 3);

    for (int i = tid; i < WF / 2; i += 512)
        ((uint4*)wf_sm)[i] = ((const uint4*)wfrag)[i];
    bias[tid] = b_ih[tid] + b_hh[tid];

    uint32_t bf[8][4][2];
#pragma unroll
    for (int g = 0; g < 4; g++) {
        int n = 128 * g + 8 * wid + r_lo;
        const float* wr = w_hh + (size_t)n * Hc + c_loc;
#pragma unroll
        for (int kt = 0; kt < 8; kt++) {
            float2 v0 = *(const float2*)(wr + kt * 16);
            float2 v1 = *(const float2*)(wr + kt * 16 + 8);
            __half2 h0 = __floats2half2_rn(v0.x, v0.y);
            __half2 h1 = __floats2half2_rn(v1.x, v1.y);
            bf[kt][g][0] = *(uint32_t*)&h0;
            bf[kt][g][1] = *(uint32_t*)&h1;
        }
    }

    for (int i = tid; i < 2 * 16 * 136; i += 512)
        h_sm[i] = __float2half(0.f);

    // prefetch window 0 (t=0,1)
    if (AF32) {
        for (int i = tid; i < 2 * 16 * CH32; i += 512) {
            int slab = i / (16 * CH32), rem = i % (16 * CH32);
            int r = rem / CH32, ch = rem % CH32;
            cpa16(su32(&xs32[((0 * 2 + slab) * 16 + r) * KP32 + ch * 4]),
                  in32 + ((size_t)(b0 + r) * Tc + slab) * K + ch * 4);
        }
    } else {
        for (int i = tid; i < 2 * 16 * CH; i += 512) {
            int slab = i / (16 * CH), rem = i % (16 * CH);
            int r = rem / CH, ch = rem % CH;
            cpa16(su32(&sbuf[((0 * 2 + slab) * 16 + r) * KP + ch * 8]),
                  in16 + ((size_t)(b0 + r) * Tc + slab) * K + ch * 8);
        }
    }
    asm volatile("cp.async.commit_group;");

    float cst[4];
#pragma unroll
    for (int j = 0; j < 4; j++) cst[j] = 0.f;

    int ph = 0;

    for (int w = 0; w < Tc / 2; w++) {
        const int cur = w & 1;
        asm volatile("cp.async.wait_group 0;");
        __syncthreads();

        // Phase A: input projection for t0, t0+1
        float accA[4][4], accB[4][4];
#pragma unroll
        for (int g = 0; g < 4; g++)
#pragma unroll
            for (int j = 0; j < 4; j++) { accA[g][j] = 0.f; accB[g][j] = 0.f; }

#pragma unroll
        for (int kt = 0; kt < KT_IH; kt++) {
            uint32_t a0[4], a1[4];
            if (AF32) {
                const float* s0 = xs32 + ((cur * 2 + 0) * 16) * KP32;
                const float* s1 = xs32 + ((cur * 2 + 1) * 16) * KP32;
                int k0 = kt * 16 + c_loc;
                a0[0] = f2h2(s0 + (r_lo    ) * KP32 + k0);
                a0[1] = f2h2(s0 + (r_lo + 8) * KP32 + k0);
                a0[2] = f2h2(s0 + (r_lo    ) * KP32 + k0 + 8);
                a0[3] = f2h2(s0 + (r_lo + 8) * KP32 + k0 + 8);
                a1[0] = f2h2(s1 + (r_lo    ) * KP32 + k0);
                a1[1] = f2h2(s1 + (r_lo + 8) * KP32 + k0);
                a1[2] = f2h2(s1 + (r_lo    ) * KP32 + k0 + 8);
                a1[3] = f2h2(s1 + (r_lo + 8) * KP32 + k0 + 8);
            } else {
                int row = (mat & 1) * 8 + lr;
                int col = kt * 16 + (mat >> 1) * 8;
                ldsm4(su32(&sbuf[((cur * 2 + 0) * 16 + row) * KP + col]),
                      a0[0], a0[1], a0[2], a0[3]);
                ldsm4(su32(&sbuf[((cur * 2 + 1) * 16 + row) * KP + col]),
                      a1[0], a1[1], a1[2], a1[3]);
            }
#pragma unroll
            for (int g = 0; g < 4; g++) {
                uint2 wv = wf_sm[((kt * 4 + g) * 16 + wid) * 32 + lane];
                mma16816(accA[g], a0, (uint32_t*)&wv);
                mma16816(accB[g], a1, (uint32_t*)&wv);
            }
        }

#pragma unroll
        for (int g = 0; g < 4; g++) {
            float2 bv = *(const float2*)&bias[128 * g + 8 * wid + c_loc];
#pragma unroll
            for (int j = 0; j < 4; j++) {
                float b = (j & 1) ? bv.y : bv.x;
                accA[g][j] += b; accB[g][j] += b;
            }
        }

        // prefetch next window (overlaps phase B)
        if (w + 1 < Tc / 2) {
            if (AF32) {
                for (int i = tid; i < 2 * 16 * CH32; i += 512) {
                    int slab = i / (16 * CH32), rem = i % (16 * CH32);
                    int r = rem / CH32, ch = rem % CH32;
                    cpa16(su32(&xs32[(((cur ^ 1) * 2 + slab) * 16 + r) * KP32 + ch * 4]),
                          in32 + ((size_t)(b0 + r) * Tc + (2 * (w + 1) + slab)) * K + ch * 4);
                }
            } else {
                for (int i = tid; i < 2 * 16 * CH; i += 512) {
                    int slab = i / (16 * CH), rem = i % (16 * CH);
                    int r = rem / CH, ch = rem % CH;
                    cpa16(su32(&sbuf[(((cur ^ 1) * 2 + slab) * 16 + r) * KP + ch * 8]),
                          in16 + ((size_t)(b0 + r) * Tc + (2 * (w + 1) + slab)) * K + ch * 8);
                }
            }
        }
        asm volatile("cp.async.commit_group;");

        // Phase B: two serial recurrence steps (only the inter-step sync kept)
#pragma unroll
        for (int s = 0; s < 2; s++) {
            float (*acc)[4] = (s == 0) ? accA : accB;
            const int t = 2 * w + s;
            if (s == 1) __syncthreads();

#pragma unroll
            for (int kt = 0; kt < 8; kt++) {
                uint32_t a[4];
                a[0] = *(const uint32_t*)&h_sm[(ph * 16 + r_lo    ) * 136 + kt * 16 + c_loc];
                a[1] = *(const uint32_t*)&h_sm[(ph * 16 + r_lo + 8) * 136 + kt * 16 + c_loc];
                a[2] = *(const uint32_t*)&h_sm[(ph * 16 + r_lo    ) * 136 + kt * 16 + c_loc + 8];
                a[3] = *(const uint32_t*)&h_sm[(ph * 16 + r_lo + 8) * 136 + kt * 16 + c_loc + 8];
#pragma unroll
                for (int g = 0; g < 4; g++) mma16816(acc[g], a, bf[kt][g]);
            }

#pragma unroll
            for (int jr = 0; jr < 2; jr++) {
                float hv0, hv1;
#pragma unroll
                for (int jc = 0; jc < 2; jc++) {
                    int j = jr * 2 + jc;
                    float i_ = sig_f(acc[0][j]);
                    float f_ = sig_f(acc[1][j]);
                    float z_ = tanh_f(acc[2][j]);
                    float o_ = sig_f(acc[3][j]);
                    float cn = fmaf(f_, cst[j], i_ * z_);
                    cst[j] = cn;
                    float hv = o_ * tanh_f(cn);
                    if (jc == 0) hv0 = hv; else hv1 = hv;
                }
                __half2 hh = __floats2half2_rn(hv0, hv1);
                int rr = r_lo + jr * 8;
                int cc = 8 * wid + c_loc;
                *(__half2*)&h_sm[((ph ^ 1) * 16 + rr) * 136 + cc] = hh;
                *(__half2*)&seqout[((size_t)(b0 + rr) * Tc + t) * Hc + cc] = hh;
            }
            ph ^= 1;
        }
    }
}

// ---------------------------------------------------------------------------
// attn_ctx: scores GEMM (aw1 frags from gmem/L2) + softmax + context -> g_ctx.
// One CTA per batch row, 256 threads, ~74KB smem -> 3 CTAs/SM.
// ---------------------------------------------------------------------------
__global__ __launch_bounds__(256)
void attn_ctx(const __half* __restrict__ seq,
              const uint2* __restrict__ wfa,
              const float* __restrict__ ab1,
              const float* __restrict__ aw2,
              const float* __restrict__ ab2,
              float* __restrict__ ctxout)
{
    extern __shared__ char smr[];
    __half* hs     = (__half*)smr;                 // [256][136]
    float*  abw    = (float*)(hs + 256 * 136);     // [256] ab1 | aw2
    float*  scores = abw + 256;                    // [256]
    float*  attnv  = scores + 256;                 // [256]
    float*  ctxp   = attnv + 256;                  // [2][128]
    float*  red    = ctxp + 256;                   // [8]

    const int b = blockIdx.x, tid = threadIdx.x;
    const int wid = tid >> 5, lane = tid & 31;
    const int mat = lane >> 3, lr = lane & 7;

    {
        const uint4* Sg = (const uint4*)(seq + (size_t)b * Tc * Hc);
        for (int i = tid; i < 256 * 16; i += 256) {
            int r = i >> 4, ch = i & 15;
            *(uint4*)(hs + r * 136 + ch * 8) = Sg[i];
        }
        if (tid < 128) abw[tid] = ab1[tid];
        else           abw[tid] = aw2[tid - 128];
    }
    __syncthreads();

    const float ab2v = ab2[0];

#pragma unroll
    for (int mt = 0; mt < 2; mt++) {
        float spa = 0.f, spb = 0.f;
#pragma unroll
        for (int nh = 0; nh < 2; nh++) {
            float acc[8][4];
#pragma unroll
            for (int nt = 0; nt < 8; nt++)
#pragma unroll
                for (int j = 0; j < 4; j++) acc[nt][j] = 0.f;

#pragma unroll
            for (int kt = 0; kt < 8; kt++) {
                uint32_t a[4];
                int row = wid * 32 + mt * 16 + (mat & 1) * 8 + lr;
                int col = kt * 16 + (mat >> 1) * 8;
                ldsm4(su32(hs + row * 136 + col), a[0], a[1], a[2], a[3]);
#pragma unroll
                for (int nq = 0; nq < 8; nq++) {
                    uint2 wv = wfa[(kt * 16 + nh * 8 + nq) * 32 + lane];
                    mma16816(acc[nq], a, (uint32_t*)&wv);
                }
            }
#pragma unroll
            for (int nt = 0; nt < 8; nt++) {
                int n = nh * 64 + nt * 8 + 2 * (lane & 3);
                float2 bb = *(float2*)&abw[n];
                float2 ww = *(float2*)&abw[128 + n];
                spa += tanh_f(acc[nt][0] + bb.x) * ww.x
                     + tanh_f(acc[nt][1] + bb.y) * ww.y;
                spb += tanh_f(acc[nt][2] + bb.x) * ww.x
                     + tanh_f(acc[nt][3] + bb.y) * ww.y;
            }
        }
        spa += __shfl_xor_sync(0xffffffffu, spa, 1);
        spa += __shfl_xor_sync(0xffffffffu, spa, 2);
        spb += __shfl_xor_sync(0xffffffffu, spb, 1);
        spb += __shfl_xor_sync(0xffffffffu, spb, 2);
        if ((lane & 3) == 0) {
            int r = wid * 32 + mt * 16 + (lane >> 2);
            scores[r]     = spa + ab2v;
            scores[r + 8] = spb + ab2v;
        }
    }
    __syncthreads();

    float sc = scores[tid];
    {
        float mx = sc;
#pragma unroll
        for (int off = 16; off > 0; off >>= 1)
            mx = fmaxf(mx, __shfl_xor_sync(0xffffffffu, mx, off));
        if (lane == 0) red[wid] = mx;
    }
    __syncthreads();
    float m8 = red[0];
#pragma unroll
    for (int w = 1; w < 8; w++) m8 = fmaxf(m8, red[w]);
    __syncthreads();
    float e = __expf(sc - m8);
    {
        float ps = e;
#pragma unroll
        for (int off = 16; off > 0; off >>= 1)
            ps += __shfl_xor_sync(0xffffffffu, ps, off);
        if (lane == 0) red[wid] = ps;
    }
    __syncthreads();
    {
        float tot = red[0] + red[1] + red[2] + red[3]
                  + red[4] + red[5] + red[6] + red[7];
        attnv[tid] = e * __fdividef(1.0f, tot);
    }
    __syncthreads();

    {
        int col = tid & 127, part = tid >> 7;
        const __half* hp = hs + (size_t)(part * 128) * 136 + col;
        const float*  pp = attnv + part * 128;
        float a = 0.f;
#pragma unroll 4
        for (int t = 0; t < 128; t++)
            a = fmaf(pp[t], __half2float(hp[(size_t)t * 136]), a);
        ctxp[part * 128 + col] = a;
    }
    __syncthreads();
    if (tid < 128)
        ctxout[(size_t)b * Hc + tid] = ctxp[tid] + ctxp[128 + tid];
}

// ---------------------------------------------------------------------------
// mlp_head: batched MLP over 32 rows per CTA (64 CTAs).
// ---------------------------------------------------------------------------
__global__ __launch_bounds__(256)
void mlp_head(const float* __restrict__ ctxin,
              const float* __restrict__ fw1, const float* __restrict__ fb1,
              const float* __restrict__ fw2, const float* __restrict__ fb2,
              const float* __restrict__ fw3, const float* __restrict__ fb3,
              float* __restrict__ out)
{
    extern __shared__ float sm[];
    float* ctxs = sm;                  // [32][128]
    float* wbuf = ctxs + 32 * 128;     // [128][129]
    float* h1s  = wbuf + 128 * 129;    // [32][132]
    float* h2s  = h1s + 32 * 132;      // [32][68]
    float* fb1s = h2s + 32 * 68;       // [128]
    float* fb2s = fb1s + 128;          // [64]
    float* fw3s = fb2s + 64;           // [64]

    const int b0 = blockIdx.x * 32;
    const int tid = threadIdx.x, wid = tid >> 5, lane = tid & 31;
    const int r0 = wid * 4;

    for (int i = tid; i < 32 * 128; i += 256)
        ctxs[i] = ctxin[(size_t)b0 * 128 + i];
    for (int i = tid; i < 128 * 128; i += 256) {
        int n = i >> 7, k = i & 127;
        wbuf[n * 129 + k] = fw1[i];
    }
    if (tid < 128) fb1s[tid] = fb1[tid];
    __syncthreads();

    {
        float a1[4][4];
#pragma unroll
        for (int m = 0; m < 4; m++) {
            float bn = fb1s[lane + 32 * m];
#pragma unroll
            for (int ri = 0; ri < 4; ri++) a1[ri][m] = bn;
        }
#pragma unroll 4
        for (int k = 0; k < 128; k++) {
            float c0 = ctxs[(r0 + 0) * 128 + k];
            float c1 = ctxs[(r0 + 1) * 128 + k];
            float c2 = ctxs[(r0 + 2) * 128 + k];
            float c3 = ctxs[(r0 + 3) * 128 + k];
#pragma unroll
            for (int m = 0; m < 4; m++) {
                float wv = wbuf[(lane + 32 * m) * 129 + k];
                a1[0][m] = fmaf(c0, wv, a1[0][m]);
                a1[1][m] = fmaf(c1, wv, a1[1][m]);
                a1[2][m] = fmaf(c2, wv, a1[2][m]);
                a1[3][m] = fmaf(c3, wv, a1[3][m]);
            }
        }
#pragma unroll
        for (int ri = 0; ri < 4; ri++)
#pragma unroll
            for (int m = 0; m < 4; m++)
                h1s[(r0 + ri) * 132 + lane + 32 * m] = fmaxf(a1[ri][m], 0.f);
    }
    __syncthreads();

    for (int i = tid; i < 64 * 128; i += 256) {
        int n = i >> 7, k = i & 127;
        wbuf[n * 129 + k] = fw2[i];
    }
    if (tid < 64) fb2s[tid] = fb2[tid];
    else if (tid < 128) fw3s[tid - 64] = fw3[tid - 64];
    __syncthreads();

    {
        float a2[4][2];
#pragma unroll
        for (int m = 0; m < 2; m++) {
            float bn = fb2s[lane + 32 * m];
#pragma unroll
            for (int ri = 0; ri < 4; ri++) a2[ri][m] = bn;
        }
#pragma unroll 4
        for (int k = 0; k < 128; k++) {
            float h0 = h1s[(r0 + 0) * 132 + k];
            float h1 = h1s[(r0 + 1) * 132 + k];
            float h2 = h1s[(r0 + 2) * 132 + k];
            float h3 = h1s[(r0 + 3) * 132 + k];
#pragma unroll
            for (int m = 0; m < 2; m++) {
                float wv = wbuf[(lane + 32 * m) * 129 + k];
                a2[0][m] = fmaf(h0, wv, a2[0][m]);
                a2[1][m] = fmaf(h1, wv, a2[1][m]);
                a2[2][m] = fmaf(h2, wv, a2[2][m]);
                a2[3][m] = fmaf(h3, wv, a2[3][m]);
            }
        }
#pragma unroll
        for (int ri = 0; ri < 4; ri++)
#pragma unroll
            for (int m = 0; m < 2; m++)
                h2s[(r0 + ri) * 68 + lane + 32 * m] = fmaxf(a2[ri][m], 0.f);
    }
    __syncthreads();

    {
        float b3 = fb3[0];
#pragma unroll
        for (int ri = 0; ri < 4; ri++) {
            int r = r0 + ri;
            float p = fw3s[lane] * h2s[r * 68 + lane]
                    + fw3s[lane + 32] * h2s[r * 68 + lane + 32];
#pragma unroll
            for (int off = 16; off > 0; off >>= 1)
                p += __shfl_xor_sync(0xffffffffu, p, off);
            if (lane == 0) out[b0 + r] = p + b3;
        }
    }
}

// ---------------------------------------------------------------------------
// Launch
// ---------------------------------------------------------------------------
extern "C" void kernel_launch(void* const* d_in, const int* in_sizes, int n_in,
                              void* d_out, int out_size)
{
    const float* x     = (const float*)d_in[0];
    const float* w_ih0 = (const float*)d_in[1];
    const float* w_hh0 = (const float*)d_in[2];
    const float* b_ih0 = (const float*)d_in[3];
    const float* b_hh0 = (const float*)d_in[4];
    const float* w_ih1 = (const float*)d_in[5];
    const float* w_hh1 = (const float*)d_in[6];
    const float* b_ih1 = (const float*)d_in[7];
    const float* b_hh1 = (const float*)d_in[8];
    const float* aw1   = (const float*)d_in[9];
    const float* ab1   = (const float*)d_in[10];
    const float* aw2   = (const float*)d_in[11];
    const float* ab2   = (const float*)d_in[12];
    const float* fw1   = (const float*)d_in[13];
    const float* fb1   = (const float*)d_in[14];
    const float* fw2   = (const float*)d_in[15];
    const float* fb2   = (const float*)d_in[16];
    const float* fw3   = (const float*)d_in[17];
    const float* fb3   = (const float*)d_in[18];
    float* out = (float*)d_out;

    __half *seq0_p, *seq1_p;
    float *ctx_p;
    uint2 *wf0_p, *wf1_p, *wfa_p;
    cudaGetSymbolAddress((void**)&seq0_p, g_seq0);
    cudaGetSymbolAddress((void**)&seq1_p, g_seq1);
    cudaGetSymbolAddress((void**)&ctx_p,  g_ctx);
    cudaGetSymbolAddress((void**)&wf0_p,  g_wf0);
    cudaGetSymbolAddress((void**)&wf1_p,  g_wf1);
    cudaGetSymbolAddress((void**)&wfa_p,  g_wfa);

    // layer0 (AF32): wf 64KB + h 8704 + xs32 [2][2][16][72]*4 = 36864 + bias 2048
    const int sm_f0 = 4 * 4 * 16 * 32 * 8 + 2 * 16 * 136 * 2 + 2 * 2 * 16 * 72 * 4 + 2048;
    // layer1 (fp16): wf 128KB + h 8704 + sbuf [2][2][16][136]*2 = 17408 + bias 2048
    const int sm_f1 = 8 * 4 * 16 * 32 * 8 + 2 * 16 * 136 * 2 + 2 * 2 * 16 * 136 * 2 + 2048;
    const int sm_ac = 256 * 136 * 2 + (256 + 256 + 256 + 256 + 8) * 4;
    const int sm_mh = (32 * 128 + 128 * 129 + 32 * 132 + 32 * 68 + 128 + 64 + 64) * 4;

    cudaFuncSetAttribute((const void*)lstm_fused<4, true>,
                         cudaFuncAttributeMaxDynamicSharedMemorySize, sm_f0);
    cudaFuncSetAttribute((const void*)lstm_fused<8, false>,
                         cudaFuncAttributeMaxDynamicSharedMemorySize, sm_f1);
    cudaFuncSetAttribute(attn_ctx, cudaFuncAttributeMaxDynamicSharedMemorySize, sm_ac);
    cudaFuncSetAttribute(mlp_head, cudaFuncAttributeMaxDynamicSharedMemorySize, sm_mh);

    // prep (weights only; x converts in-kernel now)
    fragprep<4><<<(4 * 4 * 16 * 32) / 256, 256>>>(w_ih0, wf0_p);
    fragprep<8><<<(8 * 4 * 16 * 32) / 256, 256>>>(w_ih1, wf1_p);
    fragprep_a<<<(8 * 16 * 32) / 256, 256>>>(aw1, wfa_p);

    // fused LSTM layers
    lstm_fused<4, true><<<Bc / 16, 512, sm_f0>>>(x, wf0_p, w_hh0, b_ih0, b_hh0, seq0_p);
    lstm_fused<8, false><<<Bc / 16, 512, sm_f1>>>(seq0_p, wf1_p, w_hh1, b_ih1, b_hh1, seq1_p);

    // attention context, then batched MLP head
    attn_ctx<<<Bc, 256, sm_ac>>>(seq1_p, wfa_p, ab1, aw2, ab2, ctx_p);
    mlp_head<<<Bc / 32, 256, sm_mh>>>(ctx_p, fw1, fb1, fw2, fb2, fw3, fb3, out);
}

// round 14
// speedup vs baseline: 1.0335x; 1.0335x over previous
#include <cuda_runtime.h>
#include <cuda_fp16.h>
#include <cstdint>

#define Bc 2048
#define Tc 256
#define Ic 64
#define Hc 128
#define Gc 512
#define Mc (Bc * Tc)

// ---------------------------------------------------------------------------
// Scratch (device globals; no allocation allowed)
// ---------------------------------------------------------------------------
__device__ __half g_seq0[(size_t)Mc * Hc];       // layer0 hidden [B][T][H]
__device__ __half g_seq1[(size_t)Mc * Hc];       // layer1 hidden [B][T][H]
__device__ float  g_ctx[(size_t)Bc * Hc];        // attention context [B][128]
__device__ uint2  g_wf0[4 * 4 * 16 * 32];        // w_ih0 frag-ordered (K=64)
__device__ uint2  g_wf1[8 * 4 * 16 * 32];        // w_ih1 frag-ordered (K=128)
__device__ uint2  g_wfa[8 * 16 * 32];            // aw1 frag-ordered (128x128)

// ---------------------------------------------------------------------------
// PTX helpers
// ---------------------------------------------------------------------------
__device__ __forceinline__ uint32_t su32(const void* p) {
    return (uint32_t)__cvta_generic_to_shared(p);
}
__device__ __forceinline__ void ldsm4(uint32_t a, uint32_t& r0, uint32_t& r1,
                                      uint32_t& r2, uint32_t& r3) {
    asm volatile("ldmatrix.sync.aligned.m8n8.x4.shared.b16 {%0,%1,%2,%3},[%4];"
                 : "=r"(r0), "=r"(r1), "=r"(r2), "=r"(r3) : "r"(a));
}
__device__ __forceinline__ void mma16816(float* d, const uint32_t* a, const uint32_t* b) {
    asm volatile(
        "mma.sync.aligned.m16n8k16.row.col.f32.f16.f16.f32 "
        "{%0,%1,%2,%3},{%4,%5,%6,%7},{%8,%9},{%0,%1,%2,%3};"
        : "+f"(d[0]), "+f"(d[1]), "+f"(d[2]), "+f"(d[3])
        : "r"(a[0]), "r"(a[1]), "r"(a[2]), "r"(a[3]), "r"(b[0]), "r"(b[1]));
}
__device__ __forceinline__ float tanh_f(float x) {
    float y; asm("tanh.approx.f32 %0,%1;" : "=f"(y) : "f"(x)); return y;
}
__device__ __forceinline__ float sig_f(float x) {
    return fmaf(tanh_f(0.5f * x), 0.5f, 0.5f);
}
__device__ __forceinline__ void cpa16(uint32_t d, const void* s) {
    asm volatile("cp.async.cg.shared.global [%0],[%1],16;" :: "r"(d), "l"(s));
}

// ---------------------------------------------------------------------------
// Fragment-order weight prep:  W[512][K] fp32 -> [kt][g][warp][lane]{2xu32}
// ---------------------------------------------------------------------------
template <int KT>
__global__ __launch_bounds__(256)
void fragprep(const float* __restrict__ W, uint2* __restrict__ out)
{
    int idx = blockIdx.x * 256 + threadIdx.x;
    if (idx >= KT * 4 * 16 * 32) return;
    int lane = idx & 31;
    int rest = idx >> 5;
    int w  = rest & 15; rest >>= 4;
    int g  = rest & 3;
    int kt = rest >> 2;
    int n  = 128 * g + 8 * w + (lane >> 2);
    int k0 = kt * 16 + 2 * (lane & 3);
    const float* row = W + (size_t)n * (KT * 16);
    __half2 v0 = __floats2half2_rn(row[k0],     row[k0 + 1]);
    __half2 v1 = __floats2half2_rn(row[k0 + 8], row[k0 + 9]);
    out[idx] = make_uint2(*(uint32_t*)&v0, *(uint32_t*)&v1);
}

// aw1 [128][128] fp32 -> B-frags [kt(8)][ntile(16)][lane(32)]{2xu32}
__global__ __launch_bounds__(256)
void fragprep_a(const float* __restrict__ W, uint2* __restrict__ out)
{
    int idx = blockIdx.x * 256 + threadIdx.x;   // 4096 total
    int lane = idx & 31;
    int rest = idx >> 5;
    int nt = rest & 15;
    int kt = rest >> 4;
    int n  = nt * 8 + (lane >> 2);
    int k0 = kt * 16 + 2 * (lane & 3);
    const float* row = W + (size_t)n * 128;
    __half2 v0 = __floats2half2_rn(row[k0],     row[k0 + 1]);
    __half2 v1 = __floats2half2_rn(row[k0 + 8], row[k0 + 9]);
    out[idx] = make_uint2(*(uint32_t*)&v0, *(uint32_t*)&v1);
}

// ---------------------------------------------------------------------------
// Fused LSTM layer.
// AF32=true (layer0, K=64): x fp32 is register-prefetched (1 float4/thread/
//   window via LDG), converted to fp16 at the staging STS — phase A keeps the
//   cheap ldmatrix path, no cp.async, single x buffer.
// AF32=false (layer1, K=128): fp16 input, R11 cp.async double-buffer path.
// ---------------------------------------------------------------------------
template <int KT_IH, bool AF32>
__global__ __launch_bounds__(512, 1)
void lstm_fused(const void* __restrict__ inraw,    // [B][T][K] fp32 or fp16
                const uint2* __restrict__ wfrag,   // [KT_IH][4][16][32]
                const float* __restrict__ w_hh,    // [512][128]
                const float* __restrict__ b_ih,
                const float* __restrict__ b_hh,
                __half* __restrict__ seqout)       // [B][T][128]
{
    constexpr int K  = KT_IH * 16;
    constexpr int KP = K + 8;           // fp16 staging pitch (halves)
    constexpr int CH = K / 8;           // fp16 16B chunks per row
    constexpr int WF = KT_IH * 4 * 16 * 32;
    constexpr int NSB = AF32 ? 1 : 2;   // x-buffer count (single for AF32)

    extern __shared__ char smr[];
    uint2*  wf_sm = (uint2*)smr;                         // [WF]
    __half* h_sm  = (__half*)(wf_sm + WF);               // [2][16][136]
    __half* sbuf  = h_sm + 2 * 16 * 136;                 // [NSB][2][16][KP]
    float*  bias  = (float*)(sbuf + NSB * 2 * 16 * KP);  // [512]

    const float* in32 = (const float*)inraw;
    const __half* in16 = (const __half*)inraw;

    const int tid = threadIdx.x, wid = tid >> 5, lane = tid & 31;
    const int b0 = blockIdx.x * 16;
    const int mat = lane >> 3, lr = lane & 7;
    const int r_lo = lane >> 2, c_loc = 2 * (lane & 3);

    for (int i = tid; i < WF / 2; i += 512)
        ((uint4*)wf_sm)[i] = ((const uint4*)wfrag)[i];
    bias[tid] = b_ih[tid] + b_hh[tid];

    uint32_t bf[8][4][2];
#pragma unroll
    for (int g = 0; g < 4; g++) {
        int n = 128 * g + 8 * wid + r_lo;
        const float* wr = w_hh + (size_t)n * Hc + c_loc;
#pragma unroll
        for (int kt = 0; kt < 8; kt++) {
            float2 v0 = *(const float2*)(wr + kt * 16);
            float2 v1 = *(const float2*)(wr + kt * 16 + 8);
            __half2 h0 = __floats2half2_rn(v0.x, v0.y);
            __half2 h1 = __floats2half2_rn(v1.x, v1.y);
            bf[kt][g][0] = *(uint32_t*)&h0;
            bf[kt][g][1] = *(uint32_t*)&h1;
        }
    }

    for (int i = tid; i < 2 * 16 * 136; i += 512)
        h_sm[i] = __float2half(0.f);

    // x prefetch state (AF32): one float4 per thread covers the whole window.
    // mapping: slab = tid>>8, row = (tid>>4)&15, ch = tid&15 (float4 units)
    const int xp_slab = tid >> 8;
    const int xp_row  = (tid >> 4) & 15;
    const int xp_ch   = tid & 15;
    float4 xreg;
    if (AF32) {
        xreg = *(const float4*)(in32 +
            ((size_t)(b0 + xp_row) * Tc + xp_slab) * K + xp_ch * 4);
    } else {
        // cp.async prefetch window 0 (t=0,1) into sbuf[0]
        for (int i = tid; i < 2 * 16 * CH; i += 512) {
            int slab = i / (16 * CH), rem = i % (16 * CH);
            int r = rem / CH, ch = rem % CH;
            cpa16(su32(&sbuf[((0 * 2 + slab) * 16 + r) * KP + ch * 8]),
                  in16 + ((size_t)(b0 + r) * Tc + slab) * K + ch * 8);
        }
        asm volatile("cp.async.commit_group;");
    }

    float cst[4];
#pragma unroll
    for (int j = 0; j < 4; j++) cst[j] = 0.f;

    int ph = 0;

    for (int w = 0; w < Tc / 2; w++) {
        const int cur = AF32 ? 0 : (w & 1);

        if (AF32) {
            // stage this window's x (convert in registers), then prefetch next
            __half2 hlo = __floats2half2_rn(xreg.x, xreg.y);
            __half2 hhi = __floats2half2_rn(xreg.z, xreg.w);
            *(uint2*)&sbuf[(xp_slab * 16 + xp_row) * KP + xp_ch * 4] =
                make_uint2(*(uint32_t*)&hlo, *(uint32_t*)&hhi);
            if (w + 1 < Tc / 2) {
                xreg = *(const float4*)(in32 +
                    ((size_t)(b0 + xp_row) * Tc + (2 * (w + 1) + xp_slab)) * K + xp_ch * 4);
            }
            __syncthreads();
        } else {
            asm volatile("cp.async.wait_group 0;");
            __syncthreads();
        }

        // Phase A: input projection for t0, t0+1 (ldmatrix from fp16 sbuf)
        float accA[4][4], accB[4][4];
#pragma unroll
        for (int g = 0; g < 4; g++)
#pragma unroll
            for (int j = 0; j < 4; j++) { accA[g][j] = 0.f; accB[g][j] = 0.f; }

#pragma unroll
        for (int kt = 0; kt < KT_IH; kt++) {
            uint32_t a0[4], a1[4];
            int row = (mat & 1) * 8 + lr;
            int col = kt * 16 + (mat >> 1) * 8;
            ldsm4(su32(&sbuf[((cur * 2 + 0) * 16 + row) * KP + col]),
                  a0[0], a0[1], a0[2], a0[3]);
            ldsm4(su32(&sbuf[((cur * 2 + 1) * 16 + row) * KP + col]),
                  a1[0], a1[1], a1[2], a1[3]);
#pragma unroll
            for (int g = 0; g < 4; g++) {
                uint2 wv = wf_sm[((kt * 4 + g) * 16 + wid) * 32 + lane];
                mma16816(accA[g], a0, (uint32_t*)&wv);
                mma16816(accB[g], a1, (uint32_t*)&wv);
            }
        }

#pragma unroll
        for (int g = 0; g < 4; g++) {
            float2 bv = *(const float2*)&bias[128 * g + 8 * wid + c_loc];
#pragma unroll
            for (int j = 0; j < 4; j++) {
                float b = (j & 1) ? bv.y : bv.x;
                accA[g][j] += b; accB[g][j] += b;
            }
        }

        // fp16 path: prefetch next window (overlaps phase B)
        if (!AF32) {
            if (w + 1 < Tc / 2) {
                for (int i = tid; i < 2 * 16 * CH; i += 512) {
                    int slab = i / (16 * CH), rem = i % (16 * CH);
                    int r = rem / CH, ch = rem % CH;
                    cpa16(su32(&sbuf[(((cur ^ 1) * 2 + slab) * 16 + r) * KP + ch * 8]),
                          in16 + ((size_t)(b0 + r) * Tc + (2 * (w + 1) + slab)) * K + ch * 8);
                }
            }
            asm volatile("cp.async.commit_group;");
        }

        // Phase B: two serial recurrence steps (only the inter-step sync kept)
#pragma unroll
        for (int s = 0; s < 2; s++) {
            float (*acc)[4] = (s == 0) ? accA : accB;
            const int t = 2 * w + s;
            if (s == 1) __syncthreads();

#pragma unroll
            for (int kt = 0; kt < 8; kt++) {
                uint32_t a[4];
                a[0] = *(const uint32_t*)&h_sm[(ph * 16 + r_lo    ) * 136 + kt * 16 + c_loc];
                a[1] = *(const uint32_t*)&h_sm[(ph * 16 + r_lo + 8) * 136 + kt * 16 + c_loc];
                a[2] = *(const uint32_t*)&h_sm[(ph * 16 + r_lo    ) * 136 + kt * 16 + c_loc + 8];
                a[3] = *(const uint32_t*)&h_sm[(ph * 16 + r_lo + 8) * 136 + kt * 16 + c_loc + 8];
#pragma unroll
                for (int g = 0; g < 4; g++) mma16816(acc[g], a, bf[kt][g]);
            }

#pragma unroll
            for (int jr = 0; jr < 2; jr++) {
                float hv0, hv1;
#pragma unroll
                for (int jc = 0; jc < 2; jc++) {
                    int j = jr * 2 + jc;
                    float i_ = sig_f(acc[0][j]);
                    float f_ = sig_f(acc[1][j]);
                    float z_ = tanh_f(acc[2][j]);
                    float o_ = sig_f(acc[3][j]);
                    float cn = fmaf(f_, cst[j], i_ * z_);
                    cst[j] = cn;
                    float hv = o_ * tanh_f(cn);
                    if (jc == 0) hv0 = hv; else hv1 = hv;
                }
                __half2 hh = __floats2half2_rn(hv0, hv1);
                int rr = r_lo + jr * 8;
                int cc = 8 * wid + c_loc;
                *(__half2*)&h_sm[((ph ^ 1) * 16 + rr) * 136 + cc] = hh;
                *(__half2*)&seqout[((size_t)(b0 + rr) * Tc + t) * Hc + cc] = hh;
            }
            ph ^= 1;
        }
    }
}

// ---------------------------------------------------------------------------
// attn_ctx: scores GEMM (aw1 frags from gmem/L2) + softmax + context -> g_ctx.
// ---------------------------------------------------------------------------
__global__ __launch_bounds__(256)
void attn_ctx(const __half* __restrict__ seq,
              const uint2* __restrict__ wfa,
              const float* __restrict__ ab1,
              const float* __restrict__ aw2,
              const float* __restrict__ ab2,
              float* __restrict__ ctxout)
{
    extern __shared__ char smr[];
    __half* hs     = (__half*)smr;                 // [256][136]
    float*  abw    = (float*)(hs + 256 * 136);     // [256] ab1 | aw2
    float*  scores = abw + 256;                    // [256]
    float*  attnv  = scores + 256;                 // [256]
    float*  ctxp   = attnv + 256;                  // [2][128]
    float*  red    = ctxp + 256;                   // [8]

    const int b = blockIdx.x, tid = threadIdx.x;
    const int wid = tid >> 5, lane = tid & 31;
    const int mat = lane >> 3, lr = lane & 7;

    {
        const uint4* Sg = (const uint4*)(seq + (size_t)b * Tc * Hc);
        for (int i = tid; i < 256 * 16; i += 256) {
            int r = i >> 4, ch = i & 15;
            *(uint4*)(hs + r * 136 + ch * 8) = Sg[i];
        }
        if (tid < 128) abw[tid] = ab1[tid];
        else           abw[tid] = aw2[tid - 128];
    }
    __syncthreads();

    const float ab2v = ab2[0];

#pragma unroll
    for (int mt = 0; mt < 2; mt++) {
        float spa = 0.f, spb = 0.f;
#pragma unroll
        for (int nh = 0; nh < 2; nh++) {
            float acc[8][4];
#pragma unroll
            for (int nt = 0; nt < 8; nt++)
#pragma unroll
                for (int j = 0; j < 4; j++) acc[nt][j] = 0.f;

#pragma unroll
            for (int kt = 0; kt < 8; kt++) {
                uint32_t a[4];
                int row = wid * 32 + mt * 16 + (mat & 1) * 8 + lr;
                int col = kt * 16 + (mat >> 1) * 8;
                ldsm4(su32(hs + row * 136 + col), a[0], a[1], a[2], a[3]);
#pragma unroll
                for (int nq = 0; nq < 8; nq++) {
                    uint2 wv = wfa[(kt * 16 + nh * 8 + nq) * 32 + lane];
                    mma16816(acc[nq], a, (uint32_t*)&wv);
                }
            }
#pragma unroll
            for (int nt = 0; nt < 8; nt++) {
                int n = nh * 64 + nt * 8 + 2 * (lane & 3);
                float2 bb = *(float2*)&abw[n];
                float2 ww = *(float2*)&abw[128 + n];
                spa += tanh_f(acc[nt][0] + bb.x) * ww.x
                     + tanh_f(acc[nt][1] + bb.y) * ww.y;
                spb += tanh_f(acc[nt][2] + bb.x) * ww.x
                     + tanh_f(acc[nt][3] + bb.y) * ww.y;
            }
        }
        spa += __shfl_xor_sync(0xffffffffu, spa, 1);
        spa += __shfl_xor_sync(0xffffffffu, spa, 2);
        spb += __shfl_xor_sync(0xffffffffu, spb, 1);
        spb += __shfl_xor_sync(0xffffffffu, spb, 2);
        if ((lane & 3) == 0) {
            int r = wid * 32 + mt * 16 + (lane >> 2);
            scores[r]     = spa + ab2v;
            scores[r + 8] = spb + ab2v;
        }
    }
    __syncthreads();

    float sc = scores[tid];
    {
        float mx = sc;
#pragma unroll
        for (int off = 16; off > 0; off >>= 1)
            mx = fmaxf(mx, __shfl_xor_sync(0xffffffffu, mx, off));
        if (lane == 0) red[wid] = mx;
    }
    __syncthreads();
    float m8 = red[0];
#pragma unroll
    for (int w = 1; w < 8; w++) m8 = fmaxf(m8, red[w]);
    __syncthreads();
    float e = __expf(sc - m8);
    {
        float ps = e;
#pragma unroll
        for (int off = 16; off > 0; off >>= 1)
            ps += __shfl_xor_sync(0xffffffffu, ps, off);
        if (lane == 0) red[wid] = ps;
    }
    __syncthreads();
    {
        float tot = red[0] + red[1] + red[2] + red[3]
                  + red[4] + red[5] + red[6] + red[7];
        attnv[tid] = e * __fdividef(1.0f, tot);
    }
    __syncthreads();

    {
        int col = tid & 127, part = tid >> 7;
        const __half* hp = hs + (size_t)(part * 128) * 136 + col;
        const float*  pp = attnv + part * 128;
        float a = 0.f;
#pragma unroll 4
        for (int t = 0; t < 128; t++)
            a = fmaf(pp[t], __half2float(hp[(size_t)t * 136]), a);
        ctxp[part * 128 + col] = a;
    }
    __syncthreads();
    if (tid < 128)
        ctxout[(size_t)b * Hc + tid] = ctxp[tid] + ctxp[128 + tid];
}

// ---------------------------------------------------------------------------
// mlp_head: batched MLP over 32 rows per CTA (64 CTAs).
// ---------------------------------------------------------------------------
__global__ __launch_bounds__(256)
void mlp_head(const float* __restrict__ ctxin,
              const float* __restrict__ fw1, const float* __restrict__ fb1,
              const float* __restrict__ fw2, const float* __restrict__ fb2,
              const float* __restrict__ fw3, const float* __restrict__ fb3,
              float* __restrict__ out)
{
    extern __shared__ float sm[];
    float* ctxs = sm;                  // [32][128]
    float* wbuf = ctxs + 32 * 128;     // [128][129]
    float* h1s  = wbuf + 128 * 129;    // [32][132]
    float* h2s  = h1s + 32 * 132;      // [32][68]
    float* fb1s = h2s + 32 * 68;       // [128]
    float* fb2s = fb1s + 128;          // [64]
    float* fw3s = fb2s + 64;           // [64]

    const int b0 = blockIdx.x * 32;
    const int tid = threadIdx.x, wid = tid >> 5, lane = tid & 31;
    const int r0 = wid * 4;

    for (int i = tid; i < 32 * 128; i += 256)
        ctxs[i] = ctxin[(size_t)b0 * 128 + i];
    for (int i = tid; i < 128 * 128; i += 256) {
        int n = i >> 7, k = i & 127;
        wbuf[n * 129 + k] = fw1[i];
    }
    if (tid < 128) fb1s[tid] = fb1[tid];
    __syncthreads();

    {
        float a1[4][4];
#pragma unroll
        for (int m = 0; m < 4; m++) {
            float bn = fb1s[lane + 32 * m];
#pragma unroll
            for (int ri = 0; ri < 4; ri++) a1[ri][m] = bn;
        }
#pragma unroll 4
        for (int k = 0; k < 128; k++) {
            float c0 = ctxs[(r0 + 0) * 128 + k];
            float c1 = ctxs[(r0 + 1) * 128 + k];
            float c2 = ctxs[(r0 + 2) * 128 + k];
            float c3 = ctxs[(r0 + 3) * 128 + k];
#pragma unroll
            for (int m = 0; m < 4; m++) {
                float wv = wbuf[(lane + 32 * m) * 129 + k];
                a1[0][m] = fmaf(c0, wv, a1[0][m]);
                a1[1][m] = fmaf(c1, wv, a1[1][m]);
                a1[2][m] = fmaf(c2, wv, a1[2][m]);
                a1[3][m] = fmaf(c3, wv, a1[3][m]);
            }
        }
#pragma unroll
        for (int ri = 0; ri < 4; ri++)
#pragma unroll
            for (int m = 0; m < 4; m++)
                h1s[(r0 + ri) * 132 + lane + 32 * m] = fmaxf(a1[ri][m], 0.f);
    }
    __syncthreads();

    for (int i = tid; i < 64 * 128; i += 256) {
        int n = i >> 7, k = i & 127;
        wbuf[n * 129 + k] = fw2[i];
    }
    if (tid < 64) fb2s[tid] = fb2[tid];
    else if (tid < 128) fw3s[tid - 64] = fw3[tid - 64];
    __syncthreads();

    {
        float a2[4][2];
#pragma unroll
        for (int m = 0; m < 2; m++) {
            float bn = fb2s[lane + 32 * m];
#pragma unroll
            for (int ri = 0; ri < 4; ri++) a2[ri][m] = bn;
        }
#pragma unroll 4
        for (int k = 0; k < 128; k++) {
            float h0 = h1s[(r0 + 0) * 132 + k];
            float h1 = h1s[(r0 + 1) * 132 + k];
            float h2 = h1s[(r0 + 2) * 132 + k];
            float h3 = h1s[(r0 + 3) * 132 + k];
#pragma unroll
            for (int m = 0; m < 2; m++) {
                float wv = wbuf[(lane + 32 * m) * 129 + k];
                a2[0][m] = fmaf(h0, wv, a2[0][m]);
                a2[1][m] = fmaf(h1, wv, a2[1][m]);
                a2[2][m] = fmaf(h2, wv, a2[2][m]);
                a2[3][m] = fmaf(h3, wv, a2[3][m]);
            }
        }
#pragma unroll
        for (int ri = 0; ri < 4; ri++)
#pragma unroll
            for (int m = 0; m < 2; m++)
                h2s[(r0 + ri) * 68 + lane + 32 * m] = fmaxf(a2[ri][m], 0.f);
    }
    __syncthreads();

    {
        float b3 = fb3[0];
#pragma unroll
        for (int ri = 0; ri < 4; ri++) {
            int r = r0 + ri;
            float p = fw3s[lane] * h2s[r * 68 + lane]
                    + fw3s[lane + 32] * h2s[r * 68 + lane + 32];
#pragma unroll
            for (int off = 16; off > 0; off >>= 1)
                p += __shfl_xor_sync(0xffffffffu, p, off);
            if (lane == 0) out[b0 + r] = p + b3;
        }
    }
}

// ---------------------------------------------------------------------------
// Launch
// ---------------------------------------------------------------------------
extern "C" void kernel_launch(void* const* d_in, const int* in_sizes, int n_in,
                              void* d_out, int out_size)
{
    const float* x     = (const float*)d_in[0];
    const float* w_ih0 = (const float*)d_in[1];
    const float* w_hh0 = (const float*)d_in[2];
    const float* b_ih0 = (const float*)d_in[3];
    const float* b_hh0 = (const float*)d_in[4];
    const float* w_ih1 = (const float*)d_in[5];
    const float* w_hh1 = (const float*)d_in[6];
    const float* b_ih1 = (const float*)d_in[7];
    const float* b_hh1 = (const float*)d_in[8];
    const float* aw1   = (const float*)d_in[9];
    const float* ab1   = (const float*)d_in[10];
    const float* aw2   = (const float*)d_in[11];
    const float* ab2   = (const float*)d_in[12];
    const float* fw1   = (const float*)d_in[13];
    const float* fb1   = (const float*)d_in[14];
    const float* fw2   = (const float*)d_in[15];
    const float* fb2   = (const float*)d_in[16];
    const float* fw3   = (const float*)d_in[17];
    const float* fb3   = (const float*)d_in[18];
    float* out = (float*)d_out;

    __half *seq0_p, *seq1_p;
    float *ctx_p;
    uint2 *wf0_p, *wf1_p, *wfa_p;
    cudaGetSymbolAddress((void**)&seq0_p, g_seq0);
    cudaGetSymbolAddress((void**)&seq1_p, g_seq1);
    cudaGetSymbolAddress((void**)&ctx_p,  g_ctx);
    cudaGetSymbolAddress((void**)&wf0_p,  g_wf0);
    cudaGetSymbolAddress((void**)&wf1_p,  g_wf1);
    cudaGetSymbolAddress((void**)&wfa_p,  g_wfa);

    // layer0: wf 64KB + h 8704 + sbuf [1][2][16][72]*2 = 4608 + bias 2048
    const int sm_f0 = 4 * 4 * 16 * 32 * 8 + 2 * 16 * 136 * 2 + 1 * 2 * 16 * 72 * 2 + 2048;
    // layer1: wf 128KB + h 8704 + sbuf [2][2][16][136]*2 = 17408 + bias 2048
    const int sm_f1 = 8 * 4 * 16 * 32 * 8 + 2 * 16 * 136 * 2 + 2 * 2 * 16 * 136 * 2 + 2048;
    const int sm_ac = 256 * 136 * 2 + (256 + 256 + 256 + 256 + 8) * 4;
    const int sm_mh = (32 * 128 + 128 * 129 + 32 * 132 + 32 * 68 + 128 + 64 + 64) * 4;

    cudaFuncSetAttribute((const void*)lstm_fused<4, true>,
                         cudaFuncAttributeMaxDynamicSharedMemorySize, sm_f0);
    cudaFuncSetAttribute((const void*)lstm_fused<8, false>,
                         cudaFuncAttributeMaxDynamicSharedMemorySize, sm_f1);
    cudaFuncSetAttribute(attn_ctx, cudaFuncAttributeMaxDynamicSharedMemorySize, sm_ac);
    cudaFuncSetAttribute(mlp_head, cudaFuncAttributeMaxDynamicSharedMemorySize, sm_mh);

    // prep (weights only; x converts in-kernel at staging)
    fragprep<4><<<(4 * 4 * 16 * 32) / 256, 256>>>(w_ih0, wf0_p);
    fragprep<8><<<(8 * 4 * 16 * 32) / 256, 256>>>(w_ih1, wf1_p);
    fragprep_a<<<(8 * 16 * 32) / 256, 256>>>(aw1, wfa_p);

    // fused LSTM layers
    lstm_fused<4, true><<<Bc / 16, 512, sm_f0>>>(x, wf0_p, w_hh0, b_ih0, b_hh0, seq0_p);
    lstm_fused<8, false><<<Bc / 16, 512, sm_f1>>>(seq0_p, wf1_p, w_hh1, b_ih1, b_hh1, seq1_p);

    // attention context, then batched MLP head
    attn_ctx<<<Bc, 256, sm_ac>>>(seq1_p, wfa_p, ab1, aw2, ab2, ctx_p);
    mlp_head<<<Bc / 32, 256, sm_mh>>>(ctx_p, fw1, fb1, fw2, fb2, fw3, fb3, out);
}